// round 10
// baseline (speedup 1.0000x reference)
#include <cuda_runtime.h>
#include <math.h>

#define VG  19
#define NN  608
#define LS  256
#define ROW 38912   /* 608*64 */
#define BCR 9728    /* 608*16 */
#define YPG 9961472 /* 256*608*64 */
#define NTH 608

__device__ __align__(16) float g_deg[NN];            // zero-init; re-zeroed by k_post
__device__ __align__(16) float g_Nm[32 * 361];
__device__ __align__(16) float g_dt[LS * NN * 64];
__device__ __align__(16) float g_u [LS * NN * 64];
__device__ __align__(16) float g_z [LS * NN * 64];
__device__ __align__(16) float g_B [LS * NN * 16];
__device__ __align__(16) float g_C [LS * NN * 16];
__device__ __align__(16) float g_G [LS * NN * 64];
__device__ __align__(16) float g_yp[4 * YPG];

__device__ __forceinline__ float softplusf(float x) {
    return x > 20.f ? x : log1pf(expf(x));
}

// ---------- launch 1: degree ----------
__global__ void k_deg(const int* __restrict__ ei, const float* __restrict__ ew, int E) {
    int i = blockIdx.x * blockDim.x + threadIdx.x;
    if (i < E)           atomicAdd(&g_deg[ei[E + i]], ew[i]);
    else if (i < E + NN) atomicAdd(&g_deg[i - E], 1.f);
}

// ---------- launch 2: normalized adjacency ----------
__global__ void k_nmat(const int* __restrict__ ei, const float* __restrict__ ew, int E) {
    int i = blockIdx.x * blockDim.x + threadIdx.x;
    if (i < E) {
        int s = ei[i], d = ei[E + i];
        float nm = ew[i] * rsqrtf(fmaxf(g_deg[s], 1e-12f)) * rsqrtf(fmaxf(g_deg[d], 1e-12f));
        int bb = d / VG;
        g_Nm[bb * 361 + (d - bb * VG) * VG + (s - bb * VG)] = nm;
    } else if (i < E + NN) {
        int vv = i - E;
        float r = rsqrtf(fmaxf(g_deg[vv], 1e-12f));
        g_Nm[(vv / VG) * 361 + (vv % VG) * VG + (vv % VG)] = r * r;
    }
}

// ---------- launch 3: fused projections + ub precompute, block per (t,b) ----------
__global__ void __launch_bounds__(NTH) k_preub(
    const float* __restrict__ x_in, const float* __restrict__ ipw,
    const float* __restrict__ xpw,  const float* __restrict__ dtw,
    const float* __restrict__ dtb,  const float* __restrict__ gBw,
    const float* __restrict__ gBb)
{
    __shared__ __align__(16) float wsh[4096];    // ipw^T then gBw^T
    __shared__ __align__(16) float xs[608];
    __shared__ __align__(16) float us[1216];
    __shared__ __align__(16) float uaS[1216];
    __shared__ __align__(16) float xpws[2304];   // [64 d][36 pad j]
    __shared__ __align__(16) float bBs[64];
    __shared__ __align__(16) float dtr[40];
    __shared__ __align__(16) float nm[364];

    int tb = blockIdx.x, t = tb >> 5, b = tb & 31;
    int tid = threadIdx.x;
    int v = tid >> 5, l = tid & 31;

    for (int i = tid; i < 4096; i += NTH) wsh[(i & 31) * 128 + (i >> 5)] = ipw[i];
    { int node = b * VG + v; xs[tid] = x_in[node * 8192 + t * 32 + l]; }
    for (int i = tid; i < 2176; i += NTH) { int j = i >> 6, d = i & 63; xpws[d * 36 + j] = xpw[i]; }
    for (int i = tid; i < 361; i += NTH) nm[i] = g_Nm[b * 361 + i];
    if (tid < 64) bBs[tid] = gBb[tid];
    __syncthreads();

    float u0 = 0, u1 = 0, z0 = 0, z1 = 0;
    #pragma unroll 8
    for (int k = 0; k < 32; ++k) {
        float xk = xs[v * 32 + k];
        u0 = fmaf(wsh[k * 128 + l], xk, u0);
        u1 = fmaf(wsh[k * 128 + 32 + l], xk, u1);
        z0 = fmaf(wsh[k * 128 + 64 + l], xk, z0);
        z1 = fmaf(wsh[k * 128 + 96 + l], xk, z1);
    }
    us[v * 64 + l] = u0; us[v * 64 + 32 + l] = u1;
    int gb = t * ROW + (b * VG + v) * 64;
    g_u[gb + l] = u0; g_u[gb + 32 + l] = u1;
    g_z[gb + l] = z0; g_z[gb + 32 + l] = z1;
    __syncthreads();

    for (int idx = tid; idx < 646; idx += NTH) {
        int vv = idx / 34, j = idx - vv * 34;
        float a = 0.f;
        #pragma unroll 8
        for (int d = 0; d < 64; ++d) a = fmaf(xpws[d * 36 + j], us[vv * 64 + d], a);
        if (j < 2)       dtr[vv * 2 + j] = a;
        else if (j < 18) g_B[t * BCR + (b * VG + vv) * 16 + (j - 2)] = a;
        else             g_C[t * BCR + (b * VG + vv) * 16 + (j - 18)] = a;
    }
    for (int i = tid; i < 4096; i += NTH) wsh[(i & 63) * 64 + (i >> 6)] = gBw[i];
    __syncthreads();

    float r0 = dtr[v * 2], r1 = dtr[v * 2 + 1];
    float d0 = softplusf(fmaf(r0, dtw[l * 2], fmaf(r1, dtw[l * 2 + 1], dtb[l])));
    float d1 = softplusf(fmaf(r0, dtw[(l + 32) * 2], fmaf(r1, dtw[(l + 32) * 2 + 1], dtb[l + 32])));
    g_dt[gb + l] = d0; g_dt[gb + 32 + l] = d1;

    float a0 = 0, a1 = 0;
    #pragma unroll
    for (int vp = 0; vp < VG; ++vp) {
        float n = nm[v * VG + vp];
        a0 = fmaf(n, us[vp * 64 + l], a0);
        a1 = fmaf(n, us[vp * 64 + 32 + l], a1);
    }
    uaS[v * 64 + l] = a0; uaS[v * 64 + 32 + l] = a1;
    __syncthreads();

    float gg0 = bBs[l], gg1 = bBs[l + 32];
    #pragma unroll 8
    for (int k = 0; k < 64; ++k) {
        float ua0 = uaS[v * 64 + k];
        gg0 = fmaf(wsh[k * 64 + l], ua0, gg0);
        gg1 = fmaf(wsh[k * 64 + 32 + l], ua0, gg1);
    }
    g_G[gb + l] = gg0 * d0; g_G[gb + 32 + l] = gg1 * d1;
}

// ---------- launch 4: scan, persistent, 128 CTAs ----------
// smem float offsets (all 16B aligned)
#define O_WA   0
#define O_WC   4096
#define O_NMT  8192     /* [vp][v] 19x20 pad -> 384 */
#define O_S    8576     /* 4864: S4[(v<<6)+e] float4 over n */
#define O_Q    13440    /* 4864 */
#define O_QC   18304    /* 1216: QCs[v*64+e] */
#define O_DT   19520    /* 1216: dts[v*64+e] */
#define O_G2   20736    /* 1216 */
#define O_BS   21952    /* 2 par x 20 float4 = 160 */
#define O_CS   22112    /* 160 */
#define O_CSV  22272    /* 20 */
#define SMTOT  22304

__global__ void __launch_bounds__(NTH, 1) k_scan(
    const float* __restrict__ A_log,
    const float* __restrict__ gAw, const float* __restrict__ gAb,
    const float* __restrict__ gCw, const float* __restrict__ gCb)
{
    extern __shared__ __align__(16) float sm[];
    float* WAe  = sm + O_WA;
    float* WCe  = sm + O_WC;
    float* NMT  = sm + O_NMT;
    float* QCs  = sm + O_QC;
    float* CSVs = sm + O_CSV;
    float4* S4  = (float4*)(sm + O_S);
    float4* Q4  = (float4*)(sm + O_Q);
    float4* dts4 = (float4*)(sm + O_DT);
    float4* Gs4  = (float4*)(sm + O_G2);
    float4* BSb  = (float4*)(sm + O_BS);   // BSb[par*20 + v]
    float4* CSb  = (float4*)(sm + O_CS);
    const float4* WAe4 = (const float4*)WAe;
    const float4* WCe4 = (const float4*)WCe;
    const float4* NMT4 = (const float4*)NMT;

    const int tid = threadIdx.x;
    const int b = blockIdx.x >> 2, g = blockIdx.x & 3;

    for (int i = tid; i < 4096; i += NTH) {
        WAe[i] = gAw[(i & 63) * 64 + (i >> 6)];   // WAe[k*64+e]
        WCe[i] = gCw[(i & 63) * 64 + (i >> 6)];
    }
    for (int i = tid; i < 384; i += NTH) {
        int vp = i / 20, vv = i % 20;
        NMT[i] = (vp < VG && vv < VG) ? g_Nm[b * 361 + vv * VG + vp] : 0.f;
    }

    // role constants
    const int tv = (tid < 304) ? (tid >> 4) : ((tid - 304) >> 4);
    const int eq = (tid < 304) ? (tid & 15) : ((tid - 304) & 15);

    // R-threads: A (16) + bA (4) constants. Y-threads: bC (4).
    float A00,A01,A02,A03, A10,A11,A12,A13, A20,A21,A22,A23, A30,A31,A32,A33;
    float bA0, bA1, bA2, bA3;
    float4 bc;
    if (tid < 304) {
        int e = eq * 4;
        A00 = -__expf(A_log[(e+0)*16 + g*4+0]); A01 = -__expf(A_log[(e+0)*16 + g*4+1]);
        A02 = -__expf(A_log[(e+0)*16 + g*4+2]); A03 = -__expf(A_log[(e+0)*16 + g*4+3]);
        A10 = -__expf(A_log[(e+1)*16 + g*4+0]); A11 = -__expf(A_log[(e+1)*16 + g*4+1]);
        A12 = -__expf(A_log[(e+1)*16 + g*4+2]); A13 = -__expf(A_log[(e+1)*16 + g*4+3]);
        A20 = -__expf(A_log[(e+2)*16 + g*4+0]); A21 = -__expf(A_log[(e+2)*16 + g*4+1]);
        A22 = -__expf(A_log[(e+2)*16 + g*4+2]); A23 = -__expf(A_log[(e+2)*16 + g*4+3]);
        A30 = -__expf(A_log[(e+3)*16 + g*4+0]); A31 = -__expf(A_log[(e+3)*16 + g*4+1]);
        A32 = -__expf(A_log[(e+3)*16 + g*4+2]); A33 = -__expf(A_log[(e+3)*16 + g*4+3]);
        bA0 = gAb[e]; bA1 = gAb[e+1]; bA2 = gAb[e+2]; bA3 = gAb[e+3];
    } else {
        int e = eq * 4;
        bc = make_float4(gCb[e], gCb[e+1], gCb[e+2], gCb[e+3]);
    }

    // prologue: S = s_new(0); stage C(0)/B(0) into parity 0
    if (tid < 304) {
        const float4* gdt4 = (const float4*)(g_dt + b * 1216);
        const float4* gG4  = (const float4*)(g_G  + b * 1216);
        float4 dt0 = gdt4[tv * 16 + eq];
        float4 G0  = gG4 [tv * 16 + eq];
        float4 B0  = *(const float4*)&g_B[(b * VG + tv) * 16 + g * 4];
        float4 s;
        s.x = fmaf(bA0, __expf(dt0.x * A00), G0.x * B0.x);
        s.y = fmaf(bA0, __expf(dt0.x * A01), G0.x * B0.y);
        s.z = fmaf(bA0, __expf(dt0.x * A02), G0.x * B0.z);
        s.w = fmaf(bA0, __expf(dt0.x * A03), G0.x * B0.w);
        S4[(tv << 6) + (eq << 2) + 0] = s;
        s.x = fmaf(bA1, __expf(dt0.y * A10), G0.y * B0.x);
        s.y = fmaf(bA1, __expf(dt0.y * A11), G0.y * B0.y);
        s.z = fmaf(bA1, __expf(dt0.y * A12), G0.y * B0.z);
        s.w = fmaf(bA1, __expf(dt0.y * A13), G0.y * B0.w);
        S4[(tv << 6) + (eq << 2) + 1] = s;
        s.x = fmaf(bA2, __expf(dt0.z * A20), G0.z * B0.x);
        s.y = fmaf(bA2, __expf(dt0.z * A21), G0.z * B0.y);
        s.z = fmaf(bA2, __expf(dt0.z * A22), G0.z * B0.z);
        s.w = fmaf(bA2, __expf(dt0.z * A23), G0.z * B0.w);
        S4[(tv << 6) + (eq << 2) + 2] = s;
        s.x = fmaf(bA3, __expf(dt0.w * A30), G0.w * B0.x);
        s.y = fmaf(bA3, __expf(dt0.w * A31), G0.w * B0.y);
        s.z = fmaf(bA3, __expf(dt0.w * A32), G0.w * B0.z);
        s.w = fmaf(bA3, __expf(dt0.w * A33), G0.w * B0.w);
        S4[(tv << 6) + (eq << 2) + 3] = s;
    } else {
        int j0 = tid - 304;
        if (j0 < VG) CSb[j0] = *(const float4*)&g_C[(b * VG + j0) * 16 + g * 4];
    }
    float* yout = g_yp + (size_t)g * YPG;
    __syncthreads();

    for (int t = 0; t < LS; ++t) {
        const int cur = t & 1, nxt = (t + 1) & 1;
        // ---- Phase 1: Agg (tid<320) + prefetch t+1 (tid>=320) ----
        if (tid < 320) {
            int vq = tid >> 6, ae = tid & 63;
            float4 q0 = {0,0,0,0}, q1 = q0, q2 = q0, q3 = q0;
            #pragma unroll
            for (int vp = 0; vp < VG; ++vp) {
                float4 s4 = S4[(vp << 6) + ae];
                float4 n4 = NMT4[vp * 5 + vq];
                q0.x = fmaf(n4.x, s4.x, q0.x); q0.y = fmaf(n4.x, s4.y, q0.y);
                q0.z = fmaf(n4.x, s4.z, q0.z); q0.w = fmaf(n4.x, s4.w, q0.w);
                q1.x = fmaf(n4.y, s4.x, q1.x); q1.y = fmaf(n4.y, s4.y, q1.y);
                q1.z = fmaf(n4.y, s4.z, q1.z); q1.w = fmaf(n4.y, s4.w, q1.w);
                q2.x = fmaf(n4.z, s4.x, q2.x); q2.y = fmaf(n4.z, s4.y, q2.y);
                q2.z = fmaf(n4.z, s4.z, q2.z); q2.w = fmaf(n4.z, s4.w, q2.w);
                q3.x = fmaf(n4.w, s4.x, q3.x); q3.y = fmaf(n4.w, s4.y, q3.y);
                q3.z = fmaf(n4.w, s4.z, q3.z); q3.w = fmaf(n4.w, s4.w, q3.w);
            }
            int v0 = vq * 4;
            float4 c0 = CSb[cur * 20 + v0 + 0];
            float4 c1 = CSb[cur * 20 + v0 + 1];
            float4 c2 = CSb[cur * 20 + v0 + 2];
            Q4[((v0 + 0) << 6) + ae] = q0;
            Q4[((v0 + 1) << 6) + ae] = q1;
            Q4[((v0 + 2) << 6) + ae] = q2;
            QCs[(v0 + 0) * 64 + ae] = q0.x*c0.x + q0.y*c0.y + q0.z*c0.z + q0.w*c0.w;
            QCs[(v0 + 1) * 64 + ae] = q1.x*c1.x + q1.y*c1.y + q1.z*c1.z + q1.w*c1.w;
            QCs[(v0 + 2) * 64 + ae] = q2.x*c2.x + q2.y*c2.y + q2.z*c2.z + q2.w*c2.w;
            if (vq < 4) {
                float4 c3 = CSb[cur * 20 + v0 + 3];
                Q4[((v0 + 3) << 6) + ae] = q3;
                QCs[(v0 + 3) * 64 + ae] = q3.x*c3.x + q3.y*c3.y + q3.z*c3.z + q3.w*c3.w;
            }
        } else {
            int j0 = tid - 320;   // 0..287
            int tn = (t + 1 < LS) ? t + 1 : t;
            const float4* gdt4 = (const float4*)(g_dt + tn * ROW + b * 1216);
            const float4* gG4  = (const float4*)(g_G  + tn * ROW + b * 1216);
            for (int idx = j0; idx < 304; idx += 288) {
                dts4[idx] = gdt4[idx];
                Gs4[idx]  = gG4[idx];
            }
            if (j0 < VG) {
                BSb[nxt * 20 + j0] = *(const float4*)&g_B[tn * BCR + (b * VG + j0) * 16 + g * 4];
            } else if (j0 >= 32 && j0 < 32 + VG) {
                int vv = j0 - 32;
                CSb[nxt * 20 + vv] = *(const float4*)&g_C[tn * BCR + (b * VG + vv) * 16 + g * 4];
            } else if (j0 >= 64 && j0 < 64 + VG) {
                int vv = j0 - 64;
                float4 cc = CSb[cur * 20 + vv];
                CSVs[vv] = cc.x + cc.y + cc.z + cc.w;
            }
        }
        __syncthreads();

        // ---- Phase 2: R-GEMM + fused E -> S(t+1)  ||  y-GEMM + store ----
        if (tid < 304) {
            float4 a0 = {0,0,0,0}, a1 = a0, a2 = a0, a3 = a0;
            #pragma unroll 8
            for (int k = 0; k < 64; ++k) {
                float4 w = WAe4[(k << 4) + eq];
                float4 q = Q4[(tv << 6) + k];
                a0.x = fmaf(w.x, q.x, a0.x); a0.y = fmaf(w.x, q.y, a0.y);
                a0.z = fmaf(w.x, q.z, a0.z); a0.w = fmaf(w.x, q.w, a0.w);
                a1.x = fmaf(w.y, q.x, a1.x); a1.y = fmaf(w.y, q.y, a1.y);
                a1.z = fmaf(w.y, q.z, a1.z); a1.w = fmaf(w.y, q.w, a1.w);
                a2.x = fmaf(w.z, q.x, a2.x); a2.y = fmaf(w.z, q.y, a2.y);
                a2.z = fmaf(w.z, q.z, a2.z); a2.w = fmaf(w.z, q.w, a2.w);
                a3.x = fmaf(w.w, q.x, a3.x); a3.y = fmaf(w.w, q.y, a3.y);
                a3.z = fmaf(w.w, q.z, a3.z); a3.w = fmaf(w.w, q.w, a3.w);
            }
            // fused E: S(t+1) = (R + bA)*exp(dt*A) + G*B   (dt/G/B are t+1 data)
            float4 dt4 = dts4[tv * 16 + eq];
            float4 g4  = Gs4 [tv * 16 + eq];
            float4 b4  = BSb[nxt * 20 + tv];
            float4 s;
            s.x = fmaf(a0.x + bA0, __expf(dt4.x * A00), g4.x * b4.x);
            s.y = fmaf(a0.y + bA0, __expf(dt4.x * A01), g4.x * b4.y);
            s.z = fmaf(a0.z + bA0, __expf(dt4.x * A02), g4.x * b4.z);
            s.w = fmaf(a0.w + bA0, __expf(dt4.x * A03), g4.x * b4.w);
            S4[(tv << 6) + (eq << 2) + 0] = s;
            s.x = fmaf(a1.x + bA1, __expf(dt4.y * A10), g4.y * b4.x);
            s.y = fmaf(a1.y + bA1, __expf(dt4.y * A11), g4.y * b4.y);
            s.z = fmaf(a1.z + bA1, __expf(dt4.y * A12), g4.y * b4.z);
            s.w = fmaf(a1.w + bA1, __expf(dt4.y * A13), g4.y * b4.w);
            S4[(tv << 6) + (eq << 2) + 1] = s;
            s.x = fmaf(a2.x + bA2, __expf(dt4.z * A20), g4.z * b4.x);
            s.y = fmaf(a2.y + bA2, __expf(dt4.z * A21), g4.z * b4.y);
            s.z = fmaf(a2.z + bA2, __expf(dt4.z * A22), g4.z * b4.z);
            s.w = fmaf(a2.w + bA2, __expf(dt4.z * A23), g4.z * b4.w);
            S4[(tv << 6) + (eq << 2) + 2] = s;
            s.x = fmaf(a3.x + bA3, __expf(dt4.w * A30), g4.w * b4.x);
            s.y = fmaf(a3.y + bA3, __expf(dt4.w * A31), g4.w * b4.y);
            s.z = fmaf(a3.z + bA3, __expf(dt4.w * A32), g4.w * b4.z);
            s.w = fmaf(a3.w + bA3, __expf(dt4.w * A33), g4.w * b4.w);
            S4[(tv << 6) + (eq << 2) + 3] = s;
        } else {
            float csv = CSVs[tv];
            float4 acc = make_float4(bc.x * csv, bc.y * csv, bc.z * csv, bc.w * csv);
            #pragma unroll 8
            for (int k = 0; k < 64; ++k) {
                float qc = QCs[tv * 64 + k];
                float4 w = WCe4[(k << 4) + eq];
                acc.x = fmaf(w.x, qc, acc.x); acc.y = fmaf(w.y, qc, acc.y);
                acc.z = fmaf(w.z, qc, acc.z); acc.w = fmaf(w.w, qc, acc.w);
            }
            *(float4*)(yout + (size_t)t * ROW + (b * VG + tv) * 64 + (eq << 2)) = acc;
        }
        __syncthreads();
    }
}

// ---------- launch 5: post + deg re-zero ----------
__global__ void __launch_bounds__(256) k_post(
    const float* __restrict__ Dp, const float* __restrict__ opw, float* __restrict__ out)
{
    __shared__ float ys[256];
    int tid = threadIdx.x;
    if (blockIdx.x < 3) { int i = blockIdx.x * 256 + tid; if (i < NN) g_deg[i] = 0.f; }
    int sub = tid >> 6, e = tid & 63;
    int pos = blockIdx.x * 4 + sub;
    int node = pos >> 8, t = pos & 255;
    int ib = t * ROW + node * 64 + e;
    float y = g_yp[ib] + g_yp[YPG + ib] + g_yp[2 * YPG + ib] + g_yp[3 * YPG + ib];
    y = fmaf(Dp[e], g_u[ib], y);
    float z = g_z[ib];
    y *= z / (1.f + expf(-z));
    ys[sub * 64 + e] = y;
    __syncthreads();
    if (e < 32) {
        float a = 0.f;
        #pragma unroll 8
        for (int k = 0; k < 64; ++k) a = fmaf(opw[e * 64 + k], ys[sub * 64 + k], a);
        out[pos * 32 + e] = a;
    }
}

extern "C" void kernel_launch(void* const* d_in, const int* in_sizes, int n_in,
                              void* d_out, int out_size) {
    const float* x_in = (const float*)d_in[0];
    const int*   ei   = (const int*)  d_in[1];
    const float* ew   = (const float*)d_in[2];
    const float* ipw  = (const float*)d_in[3];
    const float* xpw  = (const float*)d_in[4];
    const float* dtw  = (const float*)d_in[5];
    const float* dtb  = (const float*)d_in[6];
    const float* Alog = (const float*)d_in[7];
    const float* Dp   = (const float*)d_in[8];
    const float* opw  = (const float*)d_in[9];
    const float* gAw  = (const float*)d_in[10];
    const float* gAb  = (const float*)d_in[11];
    const float* gBw  = (const float*)d_in[12];
    const float* gBb  = (const float*)d_in[13];
    const float* gCw  = (const float*)d_in[14];
    const float* gCb  = (const float*)d_in[15];
    float* out = (float*)d_out;
    int E = in_sizes[1] / 2;

    static int smem_set = 0;
    if (!smem_set) {
        cudaFuncSetAttribute(k_scan, cudaFuncAttributeMaxDynamicSharedMemorySize, SMTOT * 4);
        smem_set = 1;
    }

    k_deg  <<<(E + NN + 255) / 256, 256>>>(ei, ew, E);
    k_nmat <<<(E + NN + 255) / 256, 256>>>(ei, ew, E);
    k_preub<<<LS * 32, NTH>>>(x_in, ipw, xpw, dtw, dtb, gBw, gBb);
    k_scan <<<128, NTH, SMTOT * 4>>>(Alog, gAw, gAb, gCw, gCb);
    k_post <<<NN * LS / 4, 256>>>(Dp, opw, out);
}